// round 13
// baseline (speedup 1.0000x reference)
#include <cuda_runtime.h>
#include <cuda_fp16.h>
#include <math.h>

#define NN 100000
#define DD 64
#define EPSN 1e-15f
#define ATANH_CLIP (1.0f - 1e-7f)
#define EMAX 1300000
#define SCANB 1024
#define NB ((NN + SCANB - 1) / SCANB)   // 98

// ---------------------------------------------------------------- scratch
__device__ __half g_h16[NN * DD]; // post-linear tangent features (fp16)
__device__ float  g_x[NN * DD];   // layer-1 tangent mean (fp32)
__device__ int    g_deg[NN];
__device__ int    g_incl[NN];
__device__ int    g_bsum[NB];
__device__ int    g_start[NN + 1];
__device__ int    g_cursor[NN];
__device__ int    g_csr[EMAX];

// ---------------------------------------------------------------- degree
__global__ void k_zero_deg() {
    int i = blockIdx.x * blockDim.x + threadIdx.x;
    if (i < NN) g_deg[i] = 0;
}

__global__ void k_deg(const int* __restrict__ dst, int E) {
    int e = blockIdx.x * blockDim.x + threadIdx.x;
    if (e < E) atomicAdd(&g_deg[__ldg(&dst[e])], 1);
}

// ---------------------------------------------------------------- scan (2-pass, measured-safe)
__global__ void k_scan_local() {
    __shared__ int ws[32];
    int tid = threadIdx.x;
    int i = blockIdx.x * SCANB + tid;
    int lane = tid & 31, wid = tid >> 5;

    int v = (i < NN) ? g_deg[i] : 0;
    int x = v;
    #pragma unroll
    for (int o = 1; o < 32; o <<= 1) {
        int y = __shfl_up_sync(0xffffffffu, x, o);
        if (lane >= o) x += y;
    }
    if (lane == 31) ws[wid] = x;
    __syncthreads();
    if (wid == 0) {
        int s = ws[lane];
        #pragma unroll
        for (int o = 1; o < 32; o <<= 1) {
            int y = __shfl_up_sync(0xffffffffu, s, o);
            if (lane >= o) s += y;
        }
        ws[lane] = s;
    }
    __syncthreads();
    int incl = x + (wid > 0 ? ws[wid - 1] : 0);
    if (i < NN) g_incl[i] = incl;
    if (tid == SCANB - 1) g_bsum[blockIdx.x] = incl;
}

__global__ void k_scan_add() {
    __shared__ int soff;
    int tid = threadIdx.x;
    if (tid < 32) {
        int s = 0;
        for (int j = tid; j < (int)blockIdx.x; j += 32) s += g_bsum[j];
        #pragma unroll
        for (int o = 16; o > 0; o >>= 1)
            s += __shfl_xor_sync(0xffffffffu, s, o);
        if (tid == 0) soff = s;
    }
    __syncthreads();
    int i = blockIdx.x * SCANB + tid;
    if (i < NN) {
        int incl = g_incl[i] + soff;
        g_start[i + 1] = incl;
        g_cursor[i] = incl - g_deg[i];
    }
    if (i == 0) g_start[0] = 0;
}

__global__ void k_fill(const int* __restrict__ src,
                       const int* __restrict__ dst, int E) {
    int e = blockIdx.x * blockDim.x + threadIdx.x;
    if (e < E) {
        int d = __ldg(&dst[e]);
        int p = atomicAdd(&g_cursor[d], 1);
        g_csr[p] = __ldg(&src[e]);
    }
}

// ---------------------------------------------------------------- fused (logmap?) + GEMM -> fp16 h
#define XPAD 68
template <bool DO_LOG>
__global__ __launch_bounds__(256)
void k_linear(const float* __restrict__ x_in,
              const float* __restrict__ W,
              const float* __restrict__ b,
              const float* __restrict__ curv) {
    extern __shared__ float smem[];
    float* Xs  = smem;
    float* WsT = smem + 128 * XPAD;

    const int tid = threadIdx.x;
    const int rowbase = blockIdx.x * 128;

    for (int idx = tid; idx < DD * DD; idx += 256) {
        int j = idx >> 6, k = idx & 63;
        WsT[k * XPAD + j] = W[idx];
    }

    const float4* in4 = reinterpret_cast<const float4*>(x_in);
    float4* Xs4 = reinterpret_cast<float4*>(Xs);
    for (int idx = tid; idx < 128 * 16; idx += 256) {
        int r = idx >> 4, c4 = idx & 15;
        int row = rowbase + r;
        float4 v = (row < NN) ? in4[(size_t)row * 16 + c4]
                              : make_float4(0.f, 0.f, 0.f, 0.f);
        Xs4[r * (XPAD / 4) + c4] = v;
    }
    __syncthreads();

    if (DO_LOG) {
        float c = fabsf(__ldg(&curv[0]));
        float sc = sqrtf(c);
        if (tid < 128) {
            float ss = 0.f;
            #pragma unroll
            for (int i = 0; i < 16; i++) {
                float4 v = Xs4[tid * (XPAD / 4) + i];
                ss += v.x * v.x + v.y * v.y + v.z * v.z + v.w * v.w;
            }
            float norm = fmaxf(sqrtf(ss), EPSN);
            float arg = fminf(sc * norm, ATANH_CLIP);
            float f = atanhf(arg) / (sc * norm);
            #pragma unroll
            for (int i = 0; i < 16; i++) {
                float4 v = Xs4[tid * (XPAD / 4) + i];
                v.x *= f; v.y *= f; v.z *= f; v.w *= f;
                Xs4[tid * (XPAD / 4) + i] = v;
            }
        }
        __syncthreads();
    }

    const int tx = tid & 15;
    const int ty = tid >> 4;
    const float4* WsT4 = reinterpret_cast<const float4*>(WsT);

    float acc[8][4];
    #pragma unroll
    for (int i = 0; i < 8; i++)
        #pragma unroll
        for (int j = 0; j < 4; j++) acc[i][j] = 0.f;

    #pragma unroll
    for (int k4 = 0; k4 < 16; k4++) {
        float4 xr[8];
        #pragma unroll
        for (int i = 0; i < 8; i++)
            xr[i] = Xs4[(ty * 8 + i) * (XPAD / 4) + k4];
        float4 wr[4];
        #pragma unroll
        for (int kk = 0; kk < 4; kk++)
            wr[kk] = WsT4[(k4 * 4 + kk) * (XPAD / 4) + tx];
        #pragma unroll
        for (int kk = 0; kk < 4; kk++) {
            #pragma unroll
            for (int i = 0; i < 8; i++) {
                float xv = (kk == 0) ? xr[i].x : (kk == 1) ? xr[i].y
                         : (kk == 2) ? xr[i].z : xr[i].w;
                acc[i][0] = fmaf(xv, wr[kk].x, acc[i][0]);
                acc[i][1] = fmaf(xv, wr[kk].y, acc[i][1]);
                acc[i][2] = fmaf(xv, wr[kk].z, acc[i][2]);
                acc[i][3] = fmaf(xv, wr[kk].w, acc[i][3]);
            }
        }
    }

    float b0 = __ldg(&b[tx * 4 + 0]);
    float b1 = __ldg(&b[tx * 4 + 1]);
    float b2 = __ldg(&b[tx * 4 + 2]);
    float b3 = __ldg(&b[tx * 4 + 3]);

    #pragma unroll
    for (int i = 0; i < 8; i++) {
        int row = rowbase + ty * 8 + i;
        if (row < NN) {
            __half2 p01 = __floats2half2_rn(acc[i][0] + b0, acc[i][1] + b1);
            __half2 p23 = __floats2half2_rn(acc[i][2] + b2, acc[i][3] + b3);
            union { __half2 h2[2]; uint2 u; } cv;
            cv.h2[0] = p01; cv.h2[1] = p23;
            *reinterpret_cast<uint2*>(&g_h16[(size_t)row * DD + tx * 4]) = cv.u;
        }
    }
}

// ---------------------------------------------------------------- gather-mean (+expmap), fp16 h
// warp per node; 4 edges concurrent (8 lanes each, LDG.128 = 8 halfs/lane)
template <bool DO_EXP>
__global__ __launch_bounds__(256)
void k_agg(float* __restrict__ x_out, const float* __restrict__ curv) {
    int tid = threadIdx.x;
    int warp = tid >> 5, lane = tid & 31;
    int node = blockIdx.x * 8 + warp;
    if (node >= NN) return;

    int rs = g_start[node];
    int re = g_start[node + 1];

    int lane8 = lane & 7;   // feature chunk: halfs [lane8*8, lane8*8+8)
    int grp   = lane >> 3;  // edge slot 0..3

    float acc[8];
    #pragma unroll
    for (int i = 0; i < 8; i++) acc[i] = 0.f;

    const uint4* h16 = reinterpret_cast<const uint4*>(g_h16);  // row = 8 uint4

    for (int eb = rs; eb < re; eb += 32) {
        int idx = eb + lane;
        int sid = (idx < re) ? g_csr[idx] : 0;
        int n = min(32, re - eb);
        int niter = (n + 3) >> 2;
        for (int k = 0; k < niter; k++) {
            int ei = 4 * k + grp;
            int s = __shfl_sync(0xffffffffu, sid, ei);
            if (ei < n) {
                uint4 v = __ldg(&h16[(size_t)s * 8 + lane8]);
                const __half2* hp = reinterpret_cast<const __half2*>(&v);
                float2 f0 = __half22float2(hp[0]);
                float2 f1 = __half22float2(hp[1]);
                float2 f2 = __half22float2(hp[2]);
                float2 f3 = __half22float2(hp[3]);
                acc[0] += f0.x; acc[1] += f0.y;
                acc[2] += f1.x; acc[3] += f1.y;
                acc[4] += f2.x; acc[5] += f2.y;
                acc[6] += f3.x; acc[7] += f3.y;
            }
        }
    }

    // combine the 4 edge groups (same feature chunk in lanes lane8, lane8+8, +16, +24)
    #pragma unroll
    for (int i = 0; i < 8; i++) {
        acc[i] += __shfl_xor_sync(0xffffffffu, acc[i], 8);
        acc[i] += __shfl_xor_sync(0xffffffffu, acc[i], 16);
    }

    float inv_deg = (re > rs) ? (1.0f / (float)(re - rs)) : 0.0f;
    float u[8];
    #pragma unroll
    for (int i = 0; i < 8; i++) u[i] = acc[i] * inv_deg;

    float factor = 1.0f;
    if (DO_EXP) {
        float ss = 0.f;
        #pragma unroll
        for (int i = 0; i < 8; i++) ss += u[i] * u[i];
        // reduce across the 8 feature-chunk lanes (within each group)
        #pragma unroll
        for (int off = 4; off > 0; off >>= 1)
            ss += __shfl_xor_sync(0xffffffffu, ss, off);
        float c = fabsf(__ldg(&curv[0]));
        float sc = sqrtf(c);
        float norm = fmaxf(sqrtf(ss), EPSN);
        factor = tanhf(sc * norm) / (sc * norm);
    }

    if (grp == 0) {
        float4* orow = reinterpret_cast<float4*>(x_out + (size_t)node * DD);
        orow[lane8 * 2 + 0] = make_float4(u[0] * factor, u[1] * factor,
                                          u[2] * factor, u[3] * factor);
        orow[lane8 * 2 + 1] = make_float4(u[4] * factor, u[5] * factor,
                                          u[6] * factor, u[7] * factor);
    }
}

// ---------------------------------------------------------------- launch
extern "C" void kernel_launch(void* const* d_in, const int* in_sizes, int n_in,
                              void* d_out, int out_size) {
    const int*   src  = (const int*)d_in[0];
    const int*   dst  = (const int*)d_in[1];
    const float* emb  = (const float*)d_in[2];
    const float* W1   = (const float*)d_in[3];
    const float* b1   = (const float*)d_in[4];
    const float* W2   = (const float*)d_in[5];
    const float* b2   = (const float*)d_in[6];
    const float* curv = (const float*)d_in[7];
    const int E = in_sizes[0];
    float* out = (float*)d_out;

    const int smem_bytes = (128 * XPAD + 64 * XPAD) * sizeof(float);
    cudaFuncSetAttribute(k_linear<true>,  cudaFuncAttributeMaxDynamicSharedMemorySize, smem_bytes);
    cudaFuncSetAttribute(k_linear<false>, cudaFuncAttributeMaxDynamicSharedMemorySize, smem_bytes);

    const int lin_blocks  = (NN + 127) / 128;
    const int node_blocks = (NN + 7) / 8;

    // CSR build interleaved with layer-1 linear (linear<true> is CSR-independent;
    // placed 4th so the ncu capture window lands on it)
    k_zero_deg<<<(NN + 255) / 256, 256>>>();
    k_deg<<<(E + 255) / 256, 256>>>(dst, E);
    k_scan_local<<<NB, SCANB>>>();
    k_linear<true><<<lin_blocks, 256, smem_bytes>>>(emb, W1, b1, curv);
    k_scan_add<<<NB, SCANB>>>();
    k_fill<<<(E + 255) / 256, 256>>>(src, dst, E);

    // layer 1 aggregation: h1 -> m1 (tangent mean; expmap/logmap roundtrip cancels)
    k_agg<false><<<node_blocks, 256>>>(g_x, curv);

    // layer 2: m1 -> h2 -> out (with expmap)
    k_linear<false><<<lin_blocks, 256, smem_bytes>>>(g_x, W2, b2, curv);
    k_agg<true><<<node_blocks, 256>>>(out, curv);
}

// round 17
// speedup vs baseline: 1.0336x; 1.0336x over previous
#include <cuda_runtime.h>
#include <cuda_fp16.h>
#include <math.h>

#define NN 100000
#define DD 64
#define EPSN 1e-15f
#define ATANH_CLIP (1.0f - 1e-7f)
#define SCANB 1024
#define NB ((NN + SCANB - 1) / SCANB)   // 98
#define DEGB 592                        // 4 blocks/SM x 148 -> guaranteed co-resident

// ---------------------------------------------------------------- scratch
__device__ __half g_h16[NN * DD]; // post-linear tangent features (fp16)
__device__ float  g_x[NN * DD];   // layer-1 tangent mean (fp32)
__device__ int    g_deg[NN];
__device__ int    g_incl[NN];
__device__ int    g_bsum[NB];
__device__ int    g_start[NN + 1];
__device__ int    g_cursor[NN];
__device__ int    g_csr[1300000];
// persistent-kernel barrier state (monotonic; reset at kernel end -> replay-safe)
__device__ unsigned g_ctrA, g_doneA;
__device__ unsigned g_ctrB, g_doneB;

// grid barrier: monotonic counter, target = phase * gridDim
__device__ __forceinline__ void gbar(unsigned* ctr, unsigned target) {
    __threadfence();
    __syncthreads();
    if (threadIdx.x == 0) {
        atomicAdd(ctr, 1u);
        while (*(volatile unsigned*)ctr < target) {}
    }
    __syncthreads();
    __threadfence();
}

__device__ __forceinline__ void greset(unsigned* ctr, unsigned* done, unsigned G) {
    __syncthreads();
    if (threadIdx.x == 0) {
        __threadfence();
        atomicAdd(done, 1u);
        if (blockIdx.x == 0) {
            while (*(volatile unsigned*)done < G) {}
            *ctr = 0u; *done = 0u;
            __threadfence();
        }
    }
}

// ---------------------------------------------------------------- persistent: zero + degree
__global__ __launch_bounds__(256)
void k_deg_p(const int* __restrict__ dst, int E) {
    const unsigned G = gridDim.x;
    const int NT = G * blockDim.x;
    const int tid = blockIdx.x * blockDim.x + threadIdx.x;

    for (int i = tid; i < NN; i += NT) g_deg[i] = 0;
    gbar(&g_ctrA, G);                       // zeros visible before counting
    for (int e = tid; e < E; e += NT)
        atomicAdd(&g_deg[__ldg(&dst[e])], 1);
    greset(&g_ctrA, &g_doneA, G);
}

// ---------------------------------------------------------------- persistent: scan + fill
__global__ __launch_bounds__(SCANB)
void k_scanfill_p(const int* __restrict__ src,
                  const int* __restrict__ dst, int E) {
    __shared__ int ws[32];
    __shared__ int soff_s;
    const unsigned G = gridDim.x;           // NB = 98 <= 148 -> single wave
    int tid = threadIdx.x, bid = blockIdx.x;
    int i = bid * SCANB + tid;
    int lane = tid & 31, wid = tid >> 5;

    // phase A: block-local inclusive scan of degrees
    int v = (i < NN) ? g_deg[i] : 0;
    int x = v;
    #pragma unroll
    for (int o = 1; o < 32; o <<= 1) {
        int y = __shfl_up_sync(0xffffffffu, x, o);
        if (lane >= o) x += y;
    }
    if (lane == 31) ws[wid] = x;
    __syncthreads();
    if (wid == 0) {
        int s = ws[lane];
        #pragma unroll
        for (int o = 1; o < 32; o <<= 1) {
            int y = __shfl_up_sync(0xffffffffu, s, o);
            if (lane >= o) s += y;
        }
        ws[lane] = s;
    }
    __syncthreads();
    int incl = x + (wid > 0 ? ws[wid - 1] : 0);
    if (i < NN) g_incl[i] = incl;
    if (tid == SCANB - 1) g_bsum[bid] = incl;

    gbar(&g_ctrB, G);                       // all bsum visible

    // phase B: block offset (sum of predecessors), row starts, cursors
    if (tid < 32) {
        int s = 0;
        for (int j = tid; j < bid; j += 32) s += g_bsum[j];
        #pragma unroll
        for (int o = 16; o > 0; o >>= 1)
            s += __shfl_xor_sync(0xffffffffu, s, o);
        if (tid == 0) soff_s = s;
    }
    __syncthreads();
    if (i < NN) {
        int p = g_incl[i] + soff_s;
        g_start[i + 1] = p;
        g_cursor[i] = p - v;
    }
    if (i == 0) g_start[0] = 0;

    gbar(&g_ctrB, 2 * G);                   // all cursors visible

    // phase C: fill CSR
    const int NT = G * SCANB;
    int gtid = bid * SCANB + tid;
    for (int e = gtid; e < E; e += NT) {
        int d = __ldg(&dst[e]);
        int p = atomicAdd(&g_cursor[d], 1);
        g_csr[p] = __ldg(&src[e]);
    }

    greset(&g_ctrB, &g_doneB, G);
}

// ---------------------------------------------------------------- fused (logmap?) + GEMM -> fp16 h
#define XPAD 68
template <bool DO_LOG>
__global__ __launch_bounds__(256)
void k_linear(const float* __restrict__ x_in,
              const float* __restrict__ W,
              const float* __restrict__ b,
              const float* __restrict__ curv) {
    extern __shared__ float smem[];
    float* Xs  = smem;
    float* WsT = smem + 128 * XPAD;

    const int tid = threadIdx.x;
    const int rowbase = blockIdx.x * 128;

    for (int idx = tid; idx < DD * DD; idx += 256) {
        int j = idx >> 6, k = idx & 63;
        WsT[k * XPAD + j] = W[idx];
    }

    const float4* in4 = reinterpret_cast<const float4*>(x_in);
    float4* Xs4 = reinterpret_cast<float4*>(Xs);
    for (int idx = tid; idx < 128 * 16; idx += 256) {
        int r = idx >> 4, c4 = idx & 15;
        int row = rowbase + r;
        float4 v = (row < NN) ? in4[(size_t)row * 16 + c4]
                              : make_float4(0.f, 0.f, 0.f, 0.f);
        Xs4[r * (XPAD / 4) + c4] = v;
    }
    __syncthreads();

    if (DO_LOG) {
        float c = fabsf(__ldg(&curv[0]));
        float sc = sqrtf(c);
        if (tid < 128) {
            float ss = 0.f;
            #pragma unroll
            for (int i = 0; i < 16; i++) {
                float4 v = Xs4[tid * (XPAD / 4) + i];
                ss += v.x * v.x + v.y * v.y + v.z * v.z + v.w * v.w;
            }
            float norm = fmaxf(sqrtf(ss), EPSN);
            float arg = fminf(sc * norm, ATANH_CLIP);
            float f = atanhf(arg) / (sc * norm);
            #pragma unroll
            for (int i = 0; i < 16; i++) {
                float4 v = Xs4[tid * (XPAD / 4) + i];
                v.x *= f; v.y *= f; v.z *= f; v.w *= f;
                Xs4[tid * (XPAD / 4) + i] = v;
            }
        }
        __syncthreads();
    }

    const int tx = tid & 15;
    const int ty = tid >> 4;
    const float4* WsT4 = reinterpret_cast<const float4*>(WsT);

    float acc[8][4];
    #pragma unroll
    for (int i = 0; i < 8; i++)
        #pragma unroll
        for (int j = 0; j < 4; j++) acc[i][j] = 0.f;

    #pragma unroll
    for (int k4 = 0; k4 < 16; k4++) {
        float4 xr[8];
        #pragma unroll
        for (int i = 0; i < 8; i++)
            xr[i] = Xs4[(ty * 8 + i) * (XPAD / 4) + k4];
        float4 wr[4];
        #pragma unroll
        for (int kk = 0; kk < 4; kk++)
            wr[kk] = WsT4[(k4 * 4 + kk) * (XPAD / 4) + tx];
        #pragma unroll
        for (int kk = 0; kk < 4; kk++) {
            #pragma unroll
            for (int i = 0; i < 8; i++) {
                float xv = (kk == 0) ? xr[i].x : (kk == 1) ? xr[i].y
                         : (kk == 2) ? xr[i].z : xr[i].w;
                acc[i][0] = fmaf(xv, wr[kk].x, acc[i][0]);
                acc[i][1] = fmaf(xv, wr[kk].y, acc[i][1]);
                acc[i][2] = fmaf(xv, wr[kk].z, acc[i][2]);
                acc[i][3] = fmaf(xv, wr[kk].w, acc[i][3]);
            }
        }
    }

    float b0 = __ldg(&b[tx * 4 + 0]);
    float b1 = __ldg(&b[tx * 4 + 1]);
    float b2 = __ldg(&b[tx * 4 + 2]);
    float b3 = __ldg(&b[tx * 4 + 3]);

    #pragma unroll
    for (int i = 0; i < 8; i++) {
        int row = rowbase + ty * 8 + i;
        if (row < NN) {
            __half2 p01 = __floats2half2_rn(acc[i][0] + b0, acc[i][1] + b1);
            __half2 p23 = __floats2half2_rn(acc[i][2] + b2, acc[i][3] + b3);
            union { __half2 h2[2]; uint2 u; } cv;
            cv.h2[0] = p01; cv.h2[1] = p23;
            *reinterpret_cast<uint2*>(&g_h16[(size_t)row * DD + tx * 4]) = cv.u;
        }
    }
}

// ---------------------------------------------------------------- gather-mean (+expmap), fp16 h
template <bool DO_EXP>
__global__ __launch_bounds__(256)
void k_agg(float* __restrict__ x_out, const float* __restrict__ curv) {
    int tid = threadIdx.x;
    int warp = tid >> 5, lane = tid & 31;
    int node = blockIdx.x * 8 + warp;
    if (node >= NN) return;

    int rs = g_start[node];
    int re = g_start[node + 1];

    int lane8 = lane & 7;   // feature chunk: halfs [lane8*8, lane8*8+8)
    int grp   = lane >> 3;  // edge slot 0..3

    float acc[8];
    #pragma unroll
    for (int i = 0; i < 8; i++) acc[i] = 0.f;

    const uint4* h16 = reinterpret_cast<const uint4*>(g_h16);  // row = 8 uint4

    for (int eb = rs; eb < re; eb += 32) {
        int idx = eb + lane;
        int sid = (idx < re) ? g_csr[idx] : 0;
        int n = min(32, re - eb);
        int niter = (n + 3) >> 2;
        for (int k = 0; k < niter; k++) {
            int ei = 4 * k + grp;
            int s = __shfl_sync(0xffffffffu, sid, ei);
            if (ei < n) {
                uint4 v = __ldg(&h16[(size_t)s * 8 + lane8]);
                const __half2* hp = reinterpret_cast<const __half2*>(&v);
                float2 f0 = __half22float2(hp[0]);
                float2 f1 = __half22float2(hp[1]);
                float2 f2 = __half22float2(hp[2]);
                float2 f3 = __half22float2(hp[3]);
                acc[0] += f0.x; acc[1] += f0.y;
                acc[2] += f1.x; acc[3] += f1.y;
                acc[4] += f2.x; acc[5] += f2.y;
                acc[6] += f3.x; acc[7] += f3.y;
            }
        }
    }

    #pragma unroll
    for (int i = 0; i < 8; i++) {
        acc[i] += __shfl_xor_sync(0xffffffffu, acc[i], 8);
        acc[i] += __shfl_xor_sync(0xffffffffu, acc[i], 16);
    }

    float inv_deg = (re > rs) ? (1.0f / (float)(re - rs)) : 0.0f;
    float u[8];
    #pragma unroll
    for (int i = 0; i < 8; i++) u[i] = acc[i] * inv_deg;

    float factor = 1.0f;
    if (DO_EXP) {
        float ss = 0.f;
        #pragma unroll
        for (int i = 0; i < 8; i++) ss += u[i] * u[i];
        #pragma unroll
        for (int off = 4; off > 0; off >>= 1)
            ss += __shfl_xor_sync(0xffffffffu, ss, off);
        float c = fabsf(__ldg(&curv[0]));
        float sc = sqrtf(c);
        float norm = fmaxf(sqrtf(ss), EPSN);
        factor = tanhf(sc * norm) / (sc * norm);
    }

    if (grp == 0) {
        float4* orow = reinterpret_cast<float4*>(x_out + (size_t)node * DD);
        orow[lane8 * 2 + 0] = make_float4(u[0] * factor, u[1] * factor,
                                          u[2] * factor, u[3] * factor);
        orow[lane8 * 2 + 1] = make_float4(u[4] * factor, u[5] * factor,
                                          u[6] * factor, u[7] * factor);
    }
}

// ---------------------------------------------------------------- launch
extern "C" void kernel_launch(void* const* d_in, const int* in_sizes, int n_in,
                              void* d_out, int out_size) {
    const int*   src  = (const int*)d_in[0];
    const int*   dst  = (const int*)d_in[1];
    const float* emb  = (const float*)d_in[2];
    const float* W1   = (const float*)d_in[3];
    const float* b1   = (const float*)d_in[4];
    const float* W2   = (const float*)d_in[5];
    const float* b2   = (const float*)d_in[6];
    const float* curv = (const float*)d_in[7];
    const int E = in_sizes[0];
    float* out = (float*)d_out;

    const int smem_bytes = (128 * XPAD + 64 * XPAD) * sizeof(float);
    cudaFuncSetAttribute(k_linear<true>,  cudaFuncAttributeMaxDynamicSharedMemorySize, smem_bytes);
    cudaFuncSetAttribute(k_linear<false>, cudaFuncAttributeMaxDynamicSharedMemorySize, smem_bytes);

    const int lin_blocks  = (NN + 127) / 128;
    const int node_blocks = (NN + 7) / 8;

    k_deg_p<<<DEGB, 256>>>(dst, E);                               // 1: zero + degree
    k_scanfill_p<<<NB, SCANB>>>(src, dst, E);                     // 2: scan + fill
    k_linear<true><<<lin_blocks, 256, smem_bytes>>>(emb, W1, b1, curv);  // 3
    k_agg<false><<<node_blocks, 256>>>(g_x, curv);                // 4  <- profiled slot
    k_linear<false><<<lin_blocks, 256, smem_bytes>>>(g_x, W2, b2, curv); // 5
    k_agg<true><<<node_blocks, 256>>>(out, curv);                 // 6
}